// round 1
// baseline (speedup 1.0000x reference)
#include <cuda_runtime.h>
#include <math.h>

#define BB 2
#define SS 4096
#define EE 768
#define HH 12
#define DD 64
#define MM (BB*SS)   // 8192 rows in the projection GEMMs

// ---------------------------------------------------------------------------
// Scratch (allocation-free: __device__ globals)
// ---------------------------------------------------------------------------
__device__ float g_Q[BB*HH*SS*DD];     // [B,H,S,64]
__device__ float g_K[BB*HH*SS*DD];
__device__ float g_V[BB*HH*SS*DD];
__device__ float g_ctx[BB*SS*EE];      // [B,S,E]

// ---------------------------------------------------------------------------
// SGEMM: C[M=8192, N=768] = A[8192,768] @ W[768,768] + bias
// 128x128 block, BK=8, 256 threads, 8x8 microtile, double-buffered smem.
// mode 0: plain row-major output.  mode 1: scatter to [B,H,S,64] head layout.
// ---------------------------------------------------------------------------
__global__ __launch_bounds__(256) void sgemm_kernel(
    const float* __restrict__ A, const float* __restrict__ W,
    const float* __restrict__ bias, float* __restrict__ C, int mode)
{
    __shared__ float As[2][8][128];   // transposed A tile
    __shared__ float Bs[2][8][128];

    const int tid    = threadIdx.x;
    const int mBlock = blockIdx.y * 128;
    const int nBlock = blockIdx.x * 128;

    const int arow = tid >> 1;          // 0..127
    const int ac4  = (tid & 1) * 4;     // 0 or 4
    const int brow = tid >> 5;          // 0..7
    const int bc4  = (tid & 31) * 4;    // 0..124

    const int ty = tid >> 4;            // 0..15
    const int tx = tid & 15;            // 0..15

    // prefetch tile 0
    float4 aReg = *(const float4*)&A[(mBlock + arow) * EE + ac4];
    float4 bReg = *(const float4*)&W[brow * EE + nBlock + bc4];

    As[0][ac4 + 0][arow] = aReg.x;
    As[0][ac4 + 1][arow] = aReg.y;
    As[0][ac4 + 2][arow] = aReg.z;
    As[0][ac4 + 3][arow] = aReg.w;
    *(float4*)&Bs[0][brow][bc4] = bReg;
    __syncthreads();

    float acc[8][8];
    #pragma unroll
    for (int i = 0; i < 8; i++)
        #pragma unroll
        for (int j = 0; j < 8; j++) acc[i][j] = 0.0f;

    int stage = 0;
    const int KSTEPS = EE / 8;   // 96
    for (int kb = 0; kb < KSTEPS; kb++) {
        if (kb < KSTEPS - 1) {
            aReg = *(const float4*)&A[(mBlock + arow) * EE + (kb + 1) * 8 + ac4];
            bReg = *(const float4*)&W[((kb + 1) * 8 + brow) * EE + nBlock + bc4];
        }

        #pragma unroll
        for (int k = 0; k < 8; k++) {
            float a[8], b[8];
            float4 t;
            t = *(const float4*)&As[stage][k][ty * 4];
            a[0] = t.x; a[1] = t.y; a[2] = t.z; a[3] = t.w;
            t = *(const float4*)&As[stage][k][64 + ty * 4];
            a[4] = t.x; a[5] = t.y; a[6] = t.z; a[7] = t.w;
            t = *(const float4*)&Bs[stage][k][tx * 4];
            b[0] = t.x; b[1] = t.y; b[2] = t.z; b[3] = t.w;
            t = *(const float4*)&Bs[stage][k][64 + tx * 4];
            b[4] = t.x; b[5] = t.y; b[6] = t.z; b[7] = t.w;

            #pragma unroll
            for (int i = 0; i < 8; i++)
                #pragma unroll
                for (int j = 0; j < 8; j++)
                    acc[i][j] = fmaf(a[i], b[j], acc[i][j]);
        }

        if (kb < KSTEPS - 1) {
            int ns = stage ^ 1;
            As[ns][ac4 + 0][arow] = aReg.x;
            As[ns][ac4 + 1][arow] = aReg.y;
            As[ns][ac4 + 2][arow] = aReg.z;
            As[ns][ac4 + 3][arow] = aReg.w;
            *(float4*)&Bs[ns][brow][bc4] = bReg;
            __syncthreads();
            stage = ns;
        }
    }

    // epilogue
    #pragma unroll
    for (int i = 0; i < 8; i++) {
        int r = (i < 4) ? (ty * 4 + i) : (64 + ty * 4 + (i - 4));
        int m = mBlock + r;
        #pragma unroll
        for (int j = 0; j < 8; j++) {
            int c = (j < 4) ? (tx * 4 + j) : (64 + tx * 4 + (j - 4));
            int e = nBlock + c;
            float v = acc[i][j] + bias[e];
            if (mode == 0) {
                C[m * EE + e] = v;
            } else {
                int bb = m >> 12;            // m / 4096
                int s  = m & 4095;
                int hh = e >> 6;             // e / 64
                int dd = e & 63;
                C[(((bb * HH) + hh) * SS + s) * DD + dd] = v;
            }
        }
    }
}

// ---------------------------------------------------------------------------
// Flash attention: per-CTA = (b, h, 64-row Q tile). Streams K/V tiles with
// online softmax. fp32 on CUDA cores. Writes ctx in [B,S,E] layout.
// Dynamic smem: Qs,Ks,Vs,Ps each 64x65 floats (padded, conflict-free).
// ---------------------------------------------------------------------------
#define LDPAD 65
__global__ __launch_bounds__(256) void flash_kernel()
{
    extern __shared__ float sm[];
    float* Qs = sm;                    // 64*65
    float* Ks = sm + 64 * LDPAD;
    float* Vs = sm + 2 * 64 * LDPAD;
    float* Ps = sm + 3 * 64 * LDPAD;

    const int tid = threadIdx.x;
    const int qt  = blockIdx.x;        // 0..63
    const int h   = blockIdx.y;        // 0..11
    const int b   = blockIdx.z;        // 0..1

    const int ty = tid >> 4;           // 0..15
    const int tx = tid & 15;           // 0..15

    const float* Qg = g_Q + (((size_t)(b * HH + h)) * SS + (size_t)qt * 64) * DD;
    const float* Kbase = g_K + ((size_t)(b * HH + h)) * SS * DD;
    const float* Vbase = g_V + ((size_t)(b * HH + h)) * SS * DD;

    // load Q tile (64x64) into padded smem
    for (int t = tid; t < 1024; t += 256) {     // float4 units
        int r  = t >> 4;
        int c4 = (t & 15) << 2;
        float4 v = *(const float4*)&Qg[r * DD + c4];
        Qs[r * LDPAD + c4 + 0] = v.x;
        Qs[r * LDPAD + c4 + 1] = v.y;
        Qs[r * LDPAD + c4 + 2] = v.z;
        Qs[r * LDPAD + c4 + 3] = v.w;
    }

    float m_i[4], l_i[4];
    float acc[4][4];
    #pragma unroll
    for (int i = 0; i < 4; i++) {
        m_i[i] = -3.0e38f;
        l_i[i] = 0.0f;
        #pragma unroll
        for (int j = 0; j < 4; j++) acc[i][j] = 0.0f;
    }

    const float scale = 0.125f;   // 1/sqrt(64)

    for (int kt = 0; kt <= qt; kt++) {
        __syncthreads();   // prior-iteration smem reads done (also covers Q load)

        // load K, V tiles
        const float* Kg = Kbase + (size_t)kt * 64 * DD;
        const float* Vg = Vbase + (size_t)kt * 64 * DD;
        for (int t = tid; t < 1024; t += 256) {
            int r  = t >> 4;
            int c4 = (t & 15) << 2;
            float4 kv = *(const float4*)&Kg[r * DD + c4];
            Ks[r * LDPAD + c4 + 0] = kv.x;
            Ks[r * LDPAD + c4 + 1] = kv.y;
            Ks[r * LDPAD + c4 + 2] = kv.z;
            Ks[r * LDPAD + c4 + 3] = kv.w;
            float4 vv = *(const float4*)&Vg[r * DD + c4];
            Vs[r * LDPAD + c4 + 0] = vv.x;
            Vs[r * LDPAD + c4 + 1] = vv.y;
            Vs[r * LDPAD + c4 + 2] = vv.z;
            Vs[r * LDPAD + c4 + 3] = vv.w;
        }
        __syncthreads();

        // scores S = Q K^T  (4x4 microtile, rows ty+16i, cols tx+16j)
        float s[4][4];
        #pragma unroll
        for (int i = 0; i < 4; i++)
            #pragma unroll
            for (int j = 0; j < 4; j++) s[i][j] = 0.0f;

        #pragma unroll 8
        for (int d = 0; d < DD; d++) {
            float qv[4], kv[4];
            #pragma unroll
            for (int i = 0; i < 4; i++) qv[i] = Qs[(ty + i * 16) * LDPAD + d];
            #pragma unroll
            for (int j = 0; j < 4; j++) kv[j] = Ks[(tx + j * 16) * LDPAD + d];
            #pragma unroll
            for (int i = 0; i < 4; i++)
                #pragma unroll
                for (int j = 0; j < 4; j++)
                    s[i][j] = fmaf(qv[i], kv[j], s[i][j]);
        }

        // scale + causal mask (only the diagonal tile needs masking)
        if (kt == qt) {
            #pragma unroll
            for (int i = 0; i < 4; i++) {
                int ri = ty + i * 16;
                #pragma unroll
                for (int j = 0; j < 4; j++) {
                    int cj = tx + j * 16;
                    s[i][j] = (cj <= ri) ? s[i][j] * scale : -1.0e30f;
                }
            }
        } else {
            #pragma unroll
            for (int i = 0; i < 4; i++)
                #pragma unroll
                for (int j = 0; j < 4; j++) s[i][j] *= scale;
        }

        // online softmax update
        float p[4][4];
        #pragma unroll
        for (int i = 0; i < 4; i++) {
            float mx = s[i][0];
            mx = fmaxf(mx, s[i][1]);
            mx = fmaxf(mx, s[i][2]);
            mx = fmaxf(mx, s[i][3]);
            #pragma unroll
            for (int o = 8; o >= 1; o >>= 1)
                mx = fmaxf(mx, __shfl_xor_sync(0xffffffffu, mx, o, 16));
            float mnew = fmaxf(m_i[i], mx);
            float corr = __expf(m_i[i] - mnew);
            m_i[i] = mnew;
            l_i[i] *= corr;
            #pragma unroll
            for (int j = 0; j < 4; j++) acc[i][j] *= corr;

            float rs = 0.0f;
            #pragma unroll
            for (int j = 0; j < 4; j++) {
                p[i][j] = __expf(s[i][j] - mnew);
                rs += p[i][j];
            }
            #pragma unroll
            for (int o = 8; o >= 1; o >>= 1)
                rs += __shfl_xor_sync(0xffffffffu, rs, o, 16);
            l_i[i] += rs;

            #pragma unroll
            for (int j = 0; j < 4; j++)
                Ps[(ty + i * 16) * LDPAD + tx + j * 16] = p[i][j];
        }
        __syncthreads();

        // O += P @ V   (cols of O are the d-dim, same tx ownership)
        #pragma unroll 8
        for (int j = 0; j < 64; j++) {
            float pv[4], vv[4];
            #pragma unroll
            for (int i = 0; i < 4; i++) pv[i] = Ps[(ty + i * 16) * LDPAD + j];
            #pragma unroll
            for (int jj = 0; jj < 4; jj++) vv[jj] = Vs[j * LDPAD + tx + jj * 16];
            #pragma unroll
            for (int i = 0; i < 4; i++)
                #pragma unroll
                for (int jj = 0; jj < 4; jj++)
                    acc[i][jj] = fmaf(pv[i], vv[jj], acc[i][jj]);
        }
    }

    // write ctx [B,S,E]
    #pragma unroll
    for (int i = 0; i < 4; i++) {
        float inv = 1.0f / l_i[i];
        int srow = qt * 64 + ty + i * 16;
        #pragma unroll
        for (int j = 0; j < 4; j++) {
            int d = tx + j * 16;
            g_ctx[((size_t)b * SS + srow) * EE + h * DD + d] = acc[i][j] * inv;
        }
    }
}

// ---------------------------------------------------------------------------
// launch
// ---------------------------------------------------------------------------
extern "C" void kernel_launch(void* const* d_in, const int* in_sizes, int n_in,
                              void* d_out, int out_size)
{
    const float* x  = (const float*)d_in[0];
    const float* Wq = (const float*)d_in[1];
    const float* bq = (const float*)d_in[2];
    const float* Wk = (const float*)d_in[3];
    const float* bk = (const float*)d_in[4];
    const float* Wv = (const float*)d_in[5];
    const float* bv = (const float*)d_in[6];
    const float* Wo = (const float*)d_in[7];
    const float* bo = (const float*)d_in[8];
    float* out = (float*)d_out;

    float *qp, *kp, *vp, *cp;
    cudaGetSymbolAddress((void**)&qp, g_Q);
    cudaGetSymbolAddress((void**)&kp, g_K);
    cudaGetSymbolAddress((void**)&vp, g_V);
    cudaGetSymbolAddress((void**)&cp, g_ctx);

    dim3 gg(EE / 128, MM / 128);   // (6, 64)
    sgemm_kernel<<<gg, 256>>>(x, Wq, bq, qp, 1);
    sgemm_kernel<<<gg, 256>>>(x, Wk, bk, kp, 1);
    sgemm_kernel<<<gg, 256>>>(x, Wv, bv, vp, 1);

    int smem = 4 * 64 * LDPAD * sizeof(float);   // 66560
    cudaFuncSetAttribute(flash_kernel, cudaFuncAttributeMaxDynamicSharedMemorySize, smem);
    dim3 fg(SS / 64, HH, BB);      // (64, 12, 2)
    flash_kernel<<<fg, 256, smem>>>();

    sgemm_kernel<<<gg, 256>>>(cp, Wo, bo, out, 0);
}

// round 11
// speedup vs baseline: 1.2180x; 1.2180x over previous
#include <cuda_runtime.h>
#include <math.h>

#define BB 2
#define SS 4096
#define EE 768
#define HH 12
#define DD 64
#define MM (BB*SS)   // 8192 rows in the projection GEMMs

// ---------------------------------------------------------------------------
// Scratch (allocation-free: __device__ globals)
// ---------------------------------------------------------------------------
__device__ float g_Q[BB*HH*SS*DD];     // [B,H,S,64]
__device__ float g_K[BB*HH*SS*DD];
__device__ float g_V[BB*HH*SS*DD];
__device__ float g_ctx[BB*SS*EE];      // [B,S,E]

// ---------------------------------------------------------------------------
// SGEMM: C[M=8192, N=768] = A[8192,768] @ W[768,768] + bias
// 128x128 block, BK=8, 256 threads, 8x8 microtile, double-buffered smem.
// mode 0: plain row-major output.  mode 1: scatter to [B,H,S,64] head layout.
// ---------------------------------------------------------------------------
__global__ __launch_bounds__(256) void sgemm_kernel(
    const float* __restrict__ A, const float* __restrict__ W,
    const float* __restrict__ bias, float* __restrict__ C, int mode)
{
    __shared__ float As[2][8][128];   // transposed A tile
    __shared__ float Bs[2][8][128];

    const int tid    = threadIdx.x;
    const int mBlock = blockIdx.y * 128;
    const int nBlock = blockIdx.x * 128;

    const int arow = tid >> 1;          // 0..127
    const int ac4  = (tid & 1) * 4;     // 0 or 4
    const int brow = tid >> 5;          // 0..7
    const int bc4  = (tid & 31) * 4;    // 0..124

    const int ty = tid >> 4;            // 0..15
    const int tx = tid & 15;            // 0..15

    // prefetch tile 0
    float4 aReg = *(const float4*)&A[(mBlock + arow) * EE + ac4];
    float4 bReg = *(const float4*)&W[brow * EE + nBlock + bc4];

    As[0][ac4 + 0][arow] = aReg.x;
    As[0][ac4 + 1][arow] = aReg.y;
    As[0][ac4 + 2][arow] = aReg.z;
    As[0][ac4 + 3][arow] = aReg.w;
    *(float4*)&Bs[0][brow][bc4] = bReg;
    __syncthreads();

    float acc[8][8];
    #pragma unroll
    for (int i = 0; i < 8; i++)
        #pragma unroll
        for (int j = 0; j < 8; j++) acc[i][j] = 0.0f;

    int stage = 0;
    const int KSTEPS = EE / 8;   // 96
    for (int kb = 0; kb < KSTEPS; kb++) {
        if (kb < KSTEPS - 1) {
            aReg = *(const float4*)&A[(mBlock + arow) * EE + (kb + 1) * 8 + ac4];
            bReg = *(const float4*)&W[((kb + 1) * 8 + brow) * EE + nBlock + bc4];
        }

        #pragma unroll
        for (int k = 0; k < 8; k++) {
            float a[8], b[8];
            float4 t;
            t = *(const float4*)&As[stage][k][ty * 4];
            a[0] = t.x; a[1] = t.y; a[2] = t.z; a[3] = t.w;
            t = *(const float4*)&As[stage][k][64 + ty * 4];
            a[4] = t.x; a[5] = t.y; a[6] = t.z; a[7] = t.w;
            t = *(const float4*)&Bs[stage][k][tx * 4];
            b[0] = t.x; b[1] = t.y; b[2] = t.z; b[3] = t.w;
            t = *(const float4*)&Bs[stage][k][64 + tx * 4];
            b[4] = t.x; b[5] = t.y; b[6] = t.z; b[7] = t.w;

            #pragma unroll
            for (int i = 0; i < 8; i++)
                #pragma unroll
                for (int j = 0; j < 8; j++)
                    acc[i][j] = fmaf(a[i], b[j], acc[i][j]);
        }

        if (kb < KSTEPS - 1) {
            int ns = stage ^ 1;
            As[ns][ac4 + 0][arow] = aReg.x;
            As[ns][ac4 + 1][arow] = aReg.y;
            As[ns][ac4 + 2][arow] = aReg.z;
            As[ns][ac4 + 3][arow] = aReg.w;
            *(float4*)&Bs[ns][brow][bc4] = bReg;
            __syncthreads();
            stage = ns;
        }
    }

    // epilogue
    #pragma unroll
    for (int i = 0; i < 8; i++) {
        int r = (i < 4) ? (ty * 4 + i) : (64 + ty * 4 + (i - 4));
        int m = mBlock + r;
        #pragma unroll
        for (int j = 0; j < 8; j++) {
            int c = (j < 4) ? (tx * 4 + j) : (64 + tx * 4 + (j - 4));
            int e = nBlock + c;
            float v = acc[i][j] + bias[e];
            if (mode == 0) {
                C[m * EE + e] = v;
            } else {
                int bb = m >> 12;            // m / 4096
                int s  = m & 4095;
                int hh = e >> 6;             // e / 64
                int dd = e & 63;
                C[(((bb * HH) + hh) * SS + s) * DD + dd] = v;
            }
        }
    }
}

// ---------------------------------------------------------------------------
// Flash attention v2: float4 LDS everywhere.
//  - K tile stored with XOR-16 swizzle so tx-strided row reads are bank-free.
//  - V tile stored plain; PV reads V as contiguous float4 row segments.
//  - Score cols use (tx + 16j) mapping; O cols use (tx*4 + c) mapping.
//    P in smem decouples the two mappings.
// smem: sQ/sK/sV 16KB each (float4[64][16]) + sP 64x68 floats = 65.4 KB.
// ---------------------------------------------------------------------------
#define LDP 68
__global__ __launch_bounds__(256) void flash_kernel()
{
    extern __shared__ float4 smem4[];
    float4* sQ = smem4;            // [64][16]
    float4* sK = smem4 + 1024;     // [64][16], xor-swizzled
    float4* sV = smem4 + 2048;     // [64][16], plain
    float*  sP = (float*)(smem4 + 3072);   // [64][LDP]

    const int tid = threadIdx.x;
    const int qt  = gridDim.x - 1 - blockIdx.x;   // longest tiles first
    const int h   = blockIdx.y;
    const int b   = blockIdx.z;

    const int ty = tid >> 4;           // 0..15
    const int tx = tid & 15;           // 0..15

    const float4* Qg = (const float4*)(g_Q + (((size_t)(b * HH + h)) * SS + (size_t)qt * 64) * DD);
    const float4* Kbase = (const float4*)(g_K + ((size_t)(b * HH + h)) * SS * DD);
    const float4* Vbase = (const float4*)(g_V + ((size_t)(b * HH + h)) * SS * DD);

    // load Q tile (64x64) -> sQ plain
    #pragma unroll
    for (int t = tid; t < 1024; t += 256) {
        int r = t >> 4;
        int c = t & 15;
        sQ[r * 16 + c] = Qg[r * 16 + c];
    }

    float m_i[4], l_i[4];
    float acc[4][4];
    #pragma unroll
    for (int i = 0; i < 4; i++) {
        m_i[i] = -3.0e38f;
        l_i[i] = 0.0f;
        #pragma unroll
        for (int j = 0; j < 4; j++) acc[i][j] = 0.0f;
    }

    const float scale = 0.125f;   // 1/sqrt(64)

    for (int kt = 0; kt <= qt; kt++) {
        __syncthreads();   // prior-iter smem reads done (also covers Q fill)

        const float4* Kg = Kbase + (size_t)kt * 64 * 16;
        const float4* Vg = Vbase + (size_t)kt * 64 * 16;
        #pragma unroll
        for (int t = tid; t < 1024; t += 256) {
            int r = t >> 4;
            int c = t & 15;
            sK[r * 16 + (c ^ (r & 15))] = Kg[r * 16 + c];
            sV[r * 16 + c]              = Vg[r * 16 + c];
        }
        __syncthreads();

        // ---- scores S = Q K^T : contraction over d, float4-vectorized ----
        float s[4][4];
        #pragma unroll
        for (int i = 0; i < 4; i++)
            #pragma unroll
            for (int j = 0; j < 4; j++) s[i][j] = 0.0f;

        #pragma unroll 4
        for (int d4 = 0; d4 < 16; d4++) {
            float4 qv[4], kv[4];
            #pragma unroll
            for (int i = 0; i < 4; i++)
                qv[i] = sQ[(ty + i * 16) * 16 + d4];
            int sx = d4 ^ tx;           // (tx+16j)&15 == tx
            #pragma unroll
            for (int j = 0; j < 4; j++)
                kv[j] = sK[(tx + j * 16) * 16 + sx];
            #pragma unroll
            for (int i = 0; i < 4; i++)
                #pragma unroll
                for (int j = 0; j < 4; j++) {
                    s[i][j] = fmaf(qv[i].x, kv[j].x, s[i][j]);
                    s[i][j] = fmaf(qv[i].y, kv[j].y, s[i][j]);
                    s[i][j] = fmaf(qv[i].z, kv[j].z, s[i][j]);
                    s[i][j] = fmaf(qv[i].w, kv[j].w, s[i][j]);
                }
        }

        // ---- scale + causal mask (diagonal tile only) ----
        if (kt == qt) {
            #pragma unroll
            for (int i = 0; i < 4; i++) {
                int ri = ty + i * 16;
                #pragma unroll
                for (int j = 0; j < 4; j++) {
                    int cj = tx + j * 16;
                    s[i][j] = (cj <= ri) ? s[i][j] * scale : -1.0e30f;
                }
            }
        } else {
            #pragma unroll
            for (int i = 0; i < 4; i++)
                #pragma unroll
                for (int j = 0; j < 4; j++) s[i][j] *= scale;
        }

        // ---- online softmax ----
        #pragma unroll
        for (int i = 0; i < 4; i++) {
            float mx = fmaxf(fmaxf(s[i][0], s[i][1]), fmaxf(s[i][2], s[i][3]));
            #pragma unroll
            for (int o = 8; o >= 1; o >>= 1)
                mx = fmaxf(mx, __shfl_xor_sync(0xffffffffu, mx, o, 16));
            float mnew = fmaxf(m_i[i], mx);
            float corr = __expf(m_i[i] - mnew);
            m_i[i] = mnew;
            l_i[i] *= corr;
            #pragma unroll
            for (int j = 0; j < 4; j++) acc[i][j] *= corr;

            float rs = 0.0f;
            #pragma unroll
            for (int j = 0; j < 4; j++) {
                s[i][j] = __expf(s[i][j] - mnew);
                rs += s[i][j];
            }
            #pragma unroll
            for (int o = 8; o >= 1; o >>= 1)
                rs += __shfl_xor_sync(0xffffffffu, rs, o, 16);
            l_i[i] += rs;

            #pragma unroll
            for (int j = 0; j < 4; j++)
                sP[(ty + i * 16) * LDP + tx + j * 16] = s[i][j];
        }
        __syncthreads();

        // ---- O += P @ V : contraction over j, float4-vectorized ----
        #pragma unroll 4
        for (int j4 = 0; j4 < 16; j4++) {
            int j = j4 * 4;
            float4 pv[4], vv[4];
            #pragma unroll
            for (int i = 0; i < 4; i++)
                pv[i] = *(const float4*)&sP[(ty + i * 16) * LDP + j];
            #pragma unroll
            for (int c = 0; c < 4; c++)
                vv[c] = sV[(j + c) * 16 + tx];
            #pragma unroll
            for (int i = 0; i < 4; i++) {
                acc[i][0] = fmaf(pv[i].x, vv[0].x, acc[i][0]);
                acc[i][0] = fmaf(pv[i].y, vv[1].x, acc[i][0]);
                acc[i][0] = fmaf(pv[i].z, vv[2].x, acc[i][0]);
                acc[i][0] = fmaf(pv[i].w, vv[3].x, acc[i][0]);
                acc[i][1] = fmaf(pv[i].x, vv[0].y, acc[i][1]);
                acc[i][1] = fmaf(pv[i].y, vv[1].y, acc[i][1]);
                acc[i][1] = fmaf(pv[i].z, vv[2].y, acc[i][1]);
                acc[i][1] = fmaf(pv[i].w, vv[3].y, acc[i][1]);
                acc[i][2] = fmaf(pv[i].x, vv[0].z, acc[i][2]);
                acc[i][2] = fmaf(pv[i].y, vv[1].z, acc[i][2]);
                acc[i][2] = fmaf(pv[i].z, vv[2].z, acc[i][2]);
                acc[i][2] = fmaf(pv[i].w, vv[3].z, acc[i][2]);
                acc[i][3] = fmaf(pv[i].x, vv[0].w, acc[i][3]);
                acc[i][3] = fmaf(pv[i].y, vv[1].w, acc[i][3]);
                acc[i][3] = fmaf(pv[i].z, vv[2].w, acc[i][3]);
                acc[i][3] = fmaf(pv[i].w, vv[3].w, acc[i][3]);
            }
        }
    }

    // ---- write ctx [B,S,E] : O cols = tx*4 + c, float4 store ----
    #pragma unroll
    for (int i = 0; i < 4; i++) {
        float inv = 1.0f / l_i[i];
        int srow = qt * 64 + ty + i * 16;
        float4 o;
        o.x = acc[i][0] * inv;
        o.y = acc[i][1] * inv;
        o.z = acc[i][2] * inv;
        o.w = acc[i][3] * inv;
        *(float4*)&g_ctx[((size_t)b * SS + srow) * EE + h * DD + tx * 4] = o;
    }
}

// ---------------------------------------------------------------------------
// launch
// ---------------------------------------------------------------------------
extern "C" void kernel_launch(void* const* d_in, const int* in_sizes, int n_in,
                              void* d_out, int out_size)
{
    const float* x  = (const float*)d_in[0];
    const float* Wq = (const float*)d_in[1];
    const float* bq = (const float*)d_in[2];
    const float* Wk = (const float*)d_in[3];
    const float* bk = (const float*)d_in[4];
    const float* Wv = (const float*)d_in[5];
    const float* bv = (const float*)d_in[6];
    const float* Wo = (const float*)d_in[7];
    const float* bo = (const float*)d_in[8];
    float* out = (float*)d_out;

    float *qp, *kp, *vp, *cp;
    cudaGetSymbolAddress((void**)&qp, g_Q);
    cudaGetSymbolAddress((void**)&kp, g_K);
    cudaGetSymbolAddress((void**)&vp, g_V);
    cudaGetSymbolAddress((void**)&cp, g_ctx);

    dim3 gg(EE / 128, MM / 128);   // (6, 64)
    sgemm_kernel<<<gg, 256>>>(x, Wq, bq, qp, 1);
    sgemm_kernel<<<gg, 256>>>(x, Wk, bk, kp, 1);
    sgemm_kernel<<<gg, 256>>>(x, Wv, bv, vp, 1);

    int smem = 3 * 1024 * sizeof(float4) + 64 * LDP * sizeof(float);   // 66560
    cudaFuncSetAttribute(flash_kernel, cudaFuncAttributeMaxDynamicSharedMemorySize, smem);
    dim3 fg(SS / 64, HH, BB);      // (64, 12, 2)
    flash_kernel<<<fg, 256, smem>>>();

    sgemm_kernel<<<gg, 256>>>(cp, Wo, bo, out, 0);
}

// round 12
// speedup vs baseline: 1.2862x; 1.0560x over previous
#include <cuda_runtime.h>
#include <math.h>

#define BB 2
#define SS 4096
#define EE 768
#define HH 12
#define DD 64
#define MM (BB*SS)

// ---------------------------------------------------------------------------
// f32x2 packed-fp32 primitives (sm_100+). Per-lane .rn -> bit-identical to fmaf.
// ---------------------------------------------------------------------------
__device__ __forceinline__ unsigned long long f2pack(float lo, float hi) {
    unsigned long long r;
    asm("mov.b64 %0, {%1, %2};" : "=l"(r) : "f"(lo), "f"(hi));
    return r;
}
__device__ __forceinline__ void f2unpack(unsigned long long v, float& lo, float& hi) {
    asm("mov.b64 {%0, %1}, %2;" : "=f"(lo), "=f"(hi) : "l"(v));
}
__device__ __forceinline__ unsigned long long f2fma(unsigned long long a,
                                                    unsigned long long b,
                                                    unsigned long long c) {
    unsigned long long d;
    asm("fma.rn.f32x2 %0, %1, %2, %3;" : "=l"(d) : "l"(a), "l"(b), "l"(c));
    return d;
}
__device__ __forceinline__ unsigned long long f2mul(unsigned long long a,
                                                    unsigned long long b) {
    unsigned long long d;
    asm("mul.rn.f32x2 %0, %1, %2;" : "=l"(d) : "l"(a), "l"(b));
    return d;
}

// ---------------------------------------------------------------------------
// Scratch (allocation-free: __device__ globals)
// ---------------------------------------------------------------------------
__device__ float g_Q[BB*HH*SS*DD];     // [B,H,S,64]
__device__ float g_K[BB*HH*SS*DD];
__device__ float g_V[BB*HH*SS*DD];
__device__ float g_ctx[BB*SS*EE];      // [B,S,E]

// ---------------------------------------------------------------------------
// SGEMM with FFMA2: C[8192,768] = A @ W + bias.
// 128x128 block, BK=8, 256 threads, 8x8 microtile via packed f32x2 (acc2[8][4]).
// B operand pairs are native (consecutive columns); A is packed via mov.b64.
// ---------------------------------------------------------------------------
__global__ __launch_bounds__(256) void sgemm_kernel(
    const float* __restrict__ A, const float* __restrict__ W,
    const float* __restrict__ bias, float* __restrict__ C, int mode)
{
    __shared__ float As[2][8][128];   // transposed A tile
    __shared__ float Bs[2][8][128];

    const int tid    = threadIdx.x;
    const int mBlock = blockIdx.y * 128;
    const int nBlock = blockIdx.x * 128;

    const int arow = tid >> 1;
    const int ac4  = (tid & 1) * 4;
    const int brow = tid >> 5;
    const int bc4  = (tid & 31) * 4;

    const int ty = tid >> 4;
    const int tx = tid & 15;

    float4 aReg = *(const float4*)&A[(mBlock + arow) * EE + ac4];
    float4 bReg = *(const float4*)&W[brow * EE + nBlock + bc4];

    As[0][ac4 + 0][arow] = aReg.x;
    As[0][ac4 + 1][arow] = aReg.y;
    As[0][ac4 + 2][arow] = aReg.z;
    As[0][ac4 + 3][arow] = aReg.w;
    *(float4*)&Bs[0][brow][bc4] = bReg;
    __syncthreads();

    unsigned long long acc2[8][4];
    #pragma unroll
    for (int i = 0; i < 8; i++)
        #pragma unroll
        for (int j = 0; j < 4; j++) acc2[i][j] = 0ull;

    int stage = 0;
    const int KSTEPS = EE / 8;   // 96
    for (int kb = 0; kb < KSTEPS; kb++) {
        if (kb < KSTEPS - 1) {
            aReg = *(const float4*)&A[(mBlock + arow) * EE + (kb + 1) * 8 + ac4];
            bReg = *(const float4*)&W[((kb + 1) * 8 + brow) * EE + nBlock + bc4];
        }

        #pragma unroll
        for (int k = 0; k < 8; k++) {
            float4 a0 = *(const float4*)&As[stage][k][ty * 4];
            float4 a1 = *(const float4*)&As[stage][k][64 + ty * 4];
            ulonglong2 b01 = *(const ulonglong2*)&Bs[stage][k][tx * 4];
            ulonglong2 b23 = *(const ulonglong2*)&Bs[stage][k][64 + tx * 4];

            unsigned long long aa[8];
            aa[0] = f2pack(a0.x, a0.x); aa[1] = f2pack(a0.y, a0.y);
            aa[2] = f2pack(a0.z, a0.z); aa[3] = f2pack(a0.w, a0.w);
            aa[4] = f2pack(a1.x, a1.x); aa[5] = f2pack(a1.y, a1.y);
            aa[6] = f2pack(a1.z, a1.z); aa[7] = f2pack(a1.w, a1.w);

            #pragma unroll
            for (int i = 0; i < 8; i++) {
                acc2[i][0] = f2fma(aa[i], b01.x, acc2[i][0]);
                acc2[i][1] = f2fma(aa[i], b01.y, acc2[i][1]);
                acc2[i][2] = f2fma(aa[i], b23.x, acc2[i][2]);
                acc2[i][3] = f2fma(aa[i], b23.y, acc2[i][3]);
            }
        }

        if (kb < KSTEPS - 1) {
            int ns = stage ^ 1;
            As[ns][ac4 + 0][arow] = aReg.x;
            As[ns][ac4 + 1][arow] = aReg.y;
            As[ns][ac4 + 2][arow] = aReg.z;
            As[ns][ac4 + 3][arow] = aReg.w;
            *(float4*)&Bs[ns][brow][bc4] = bReg;
            __syncthreads();
            stage = ns;
        }
    }

    // epilogue: unpack acc2 -> 8 columns per row
    #pragma unroll
    for (int i = 0; i < 8; i++) {
        int r = (i < 4) ? (ty * 4 + i) : (64 + ty * 4 + (i - 4));
        int m = mBlock + r;
        float cvals[8];
        f2unpack(acc2[i][0], cvals[0], cvals[1]);
        f2unpack(acc2[i][1], cvals[2], cvals[3]);
        f2unpack(acc2[i][2], cvals[4], cvals[5]);
        f2unpack(acc2[i][3], cvals[6], cvals[7]);
        #pragma unroll
        for (int j = 0; j < 8; j++) {
            int c = (j < 4) ? (tx * 4 + j) : (64 + tx * 4 + (j - 4));
            int e = nBlock + c;
            float v = cvals[j] + bias[e];
            if (mode == 0) {
                C[m * EE + e] = v;
            } else {
                int bb = m >> 12;
                int s  = m & 4095;
                int hh = e >> 6;
                int dd = e & 63;
                C[(((bb * HH) + hh) * SS + s) * DD + dd] = v;
            }
        }
    }
}

// ---------------------------------------------------------------------------
// Flash attention v3: 128x128 score tile, 256 threads, blocked 8x8 microtile,
// FFMA2 compute, d-major (transposed) Q/K in smem for broadcast-heavy reads.
//  - sQT/sKT: [64 d][132 f] transposed, conflict-free warp-dense transpose.
//  - sV: [128 k][16 float4] natural; PV d-pairs come free as ulonglong2.
//  - sP: [128 q][144 f]; PV q-broadcast float4 reads.
// smem = 33792 + 33792 + 32768 + 73728 = 174080 B -> 1 CTA/SM (intended).
// ---------------------------------------------------------------------------
#define SQT_STRIDE 132
#define SP_STRIDE  144
#define SQT_F (64 * SQT_STRIDE)       // 8448
#define SV_F  (128 * 64)              // 8192
#define SP_F  (128 * SP_STRIDE)       // 18432
#define FLASH_SMEM_BYTES ((SQT_F + SQT_F + SV_F + SP_F) * 4)   // 174080

__global__ __launch_bounds__(256) void flash_kernel()
{
    extern __shared__ float smf[];
    float*  sQT = smf;                         // [64][132]
    float*  sKT = smf + SQT_F;                 // [64][132]
    float*  sVf = smf + 2 * SQT_F;             // [128][64] (float4-viewed)
    float*  sP  = smf + 2 * SQT_F + SV_F;      // [128][144]
    float4* sV4 = (float4*)sVf;

    const int tid = threadIdx.x;
    const int qt  = gridDim.x - 1 - blockIdx.x;   // longest tiles first
    const int h   = blockIdx.y;
    const int b   = blockIdx.z;

    const int ty = tid >> 4;           // 0..15 -> q rows ty*8..ty*8+7
    const int tx = tid & 15;           // 0..15 -> k cols tx*8..+7 ; O d cols tx*4..+3

    const float4* Qg4 = (const float4*)(g_Q + (((size_t)(b * HH + h)) * SS + (size_t)qt * 128) * DD);
    const float4* Kb4 = (const float4*)(g_K + ((size_t)(b * HH + h)) * SS * DD);
    const float4* Vb4 = (const float4*)(g_V + ((size_t)(b * HH + h)) * SS * DD);

    // ---- load Q tile transposed: sQT[d][q] (warp-dense conflict-free stores) ----
    #pragma unroll
    for (int rep = 0; rep < 8; rep++) {
        int t  = tid + rep * 256;      // 0..2047
        int q  = t & 127;
        int d4 = t >> 7;               // 0..15
        float4 v = Qg4[q * 16 + d4];
        int base = (4 * d4) * SQT_STRIDE + q;
        sQT[base]                  = v.x;
        sQT[base + SQT_STRIDE]     = v.y;
        sQT[base + 2 * SQT_STRIDE] = v.z;
        sQT[base + 3 * SQT_STRIDE] = v.w;
    }

    float m_i[8], l_i[8];
    unsigned long long acc2[8][2];     // O pairs: [i][0]=(d0,d1), [i][1]=(d2,d3) of cols tx*4..
    #pragma unroll
    for (int i = 0; i < 8; i++) {
        m_i[i] = -3.0e38f;
        l_i[i] = 0.0f;
        acc2[i][0] = 0ull;
        acc2[i][1] = 0ull;
    }

    const float scale = 0.125f;   // 1/sqrt(64)

    for (int kt = 0; kt <= qt; kt++) {
        __syncthreads();   // prior-iter PV reads done (also covers Q transpose on iter 0)

        // ---- load K tile transposed + V tile straight ----
        const float4* Kg4 = Kb4 + (size_t)kt * 128 * 16;
        const float4* Vg4 = Vb4 + (size_t)kt * 128 * 16;
        #pragma unroll
        for (int rep = 0; rep < 8; rep++) {
            int t  = tid + rep * 256;
            int k  = t & 127;
            int d4 = t >> 7;
            float4 v = Kg4[k * 16 + d4];
            int base = (4 * d4) * SQT_STRIDE + k;
            sKT[base]                  = v.x;
            sKT[base + SQT_STRIDE]     = v.y;
            sKT[base + 2 * SQT_STRIDE] = v.z;
            sKT[base + 3 * SQT_STRIDE] = v.w;
            sV4[t] = Vg4[t];
        }
        __syncthreads();

        // ---- scores: S = Q K^T, FFMA2, contraction over d ----
        unsigned long long s2[8][4];   // [i][jp]: cols (tx*8+2jp, tx*8+2jp+1)
        #pragma unroll
        for (int i = 0; i < 8; i++)
            #pragma unroll
            for (int jp = 0; jp < 4; jp++) s2[i][jp] = 0ull;

        #pragma unroll 8
        for (int d = 0; d < DD; d++) {
            float4 q0 = *(const float4*)&sQT[d * SQT_STRIDE + ty * 8];
            float4 q1 = *(const float4*)&sQT[d * SQT_STRIDE + ty * 8 + 4];
            ulonglong2 k01 = *(const ulonglong2*)&sKT[d * SQT_STRIDE + tx * 8];
            ulonglong2 k23 = *(const ulonglong2*)&sKT[d * SQT_STRIDE + tx * 8 + 4];

            unsigned long long qq[8];
            qq[0] = f2pack(q0.x, q0.x); qq[1] = f2pack(q0.y, q0.y);
            qq[2] = f2pack(q0.z, q0.z); qq[3] = f2pack(q0.w, q0.w);
            qq[4] = f2pack(q1.x, q1.x); qq[5] = f2pack(q1.y, q1.y);
            qq[6] = f2pack(q1.z, q1.z); qq[7] = f2pack(q1.w, q1.w);

            #pragma unroll
            for (int i = 0; i < 8; i++) {
                s2[i][0] = f2fma(qq[i], k01.x, s2[i][0]);
                s2[i][1] = f2fma(qq[i], k01.y, s2[i][1]);
                s2[i][2] = f2fma(qq[i], k23.x, s2[i][2]);
                s2[i][3] = f2fma(qq[i], k23.y, s2[i][3]);
            }
        }

        // ---- unpack, scale + causal mask ----
        float p[8][8];
        #pragma unroll
        for (int i = 0; i < 8; i++) {
            f2unpack(s2[i][0], p[i][0], p[i][1]);
            f2unpack(s2[i][1], p[i][2], p[i][3]);
            f2unpack(s2[i][2], p[i][4], p[i][5]);
            f2unpack(s2[i][3], p[i][6], p[i][7]);
        }
        if (kt == qt) {
            #pragma unroll
            for (int i = 0; i < 8; i++) {
                int ri = ty * 8 + i;
                #pragma unroll
                for (int j = 0; j < 8; j++) {
                    int cj = tx * 8 + j;
                    p[i][j] = (cj <= ri) ? p[i][j] * scale : -1.0e30f;
                }
            }
        } else {
            #pragma unroll
            for (int i = 0; i < 8; i++)
                #pragma unroll
                for (int j = 0; j < 8; j++) p[i][j] *= scale;
        }

        // ---- online softmax (row groups = 16 tx lanes, half-warp shfl) ----
        #pragma unroll
        for (int i = 0; i < 8; i++) {
            float mx = p[i][0];
            #pragma unroll
            for (int j = 1; j < 8; j++) mx = fmaxf(mx, p[i][j]);
            #pragma unroll
            for (int o = 8; o >= 1; o >>= 1)
                mx = fmaxf(mx, __shfl_xor_sync(0xffffffffu, mx, o, 16));
            float mnew = fmaxf(m_i[i], mx);
            float corr = __expf(m_i[i] - mnew);
            m_i[i] = mnew;
            l_i[i] *= corr;
            unsigned long long corr2 = f2pack(corr, corr);
            acc2[i][0] = f2mul(acc2[i][0], corr2);
            acc2[i][1] = f2mul(acc2[i][1], corr2);

            float rs = 0.0f;
            #pragma unroll
            for (int j = 0; j < 8; j++) {
                p[i][j] = __expf(p[i][j] - mnew);
                rs += p[i][j];
            }
            #pragma unroll
            for (int o = 8; o >= 1; o >>= 1)
                rs += __shfl_xor_sync(0xffffffffu, rs, o, 16);
            l_i[i] += rs;

            // write P row segment (cols tx*8..+7) as two float4
            float* prow = &sP[(ty * 8 + i) * SP_STRIDE + tx * 8];
            *(float4*)prow       = make_float4(p[i][0], p[i][1], p[i][2], p[i][3]);
            *(float4*)(prow + 4) = make_float4(p[i][4], p[i][5], p[i][6], p[i][7]);
        }
        __syncthreads();

        // ---- O += P @ V : FFMA2, contraction over k (4 at a time) ----
        #pragma unroll 4
        for (int j4 = 0; j4 < 32; j4++) {
            float4 pv[8];
            #pragma unroll
            for (int i = 0; i < 8; i++)
                pv[i] = *(const float4*)&sP[(ty * 8 + i) * SP_STRIDE + j4 * 4];
            ulonglong2 vv[4];
            #pragma unroll
            for (int jj = 0; jj < 4; jj++)
                vv[jj] = *(const ulonglong2*)&sVf[((j4 * 4 + jj) * 16 + tx) * 4];

            #pragma unroll
            for (int i = 0; i < 8; i++) {
                unsigned long long pp;
                pp = f2pack(pv[i].x, pv[i].x);
                acc2[i][0] = f2fma(pp, vv[0].x, acc2[i][0]);
                acc2[i][1] = f2fma(pp, vv[0].y, acc2[i][1]);
                pp = f2pack(pv[i].y, pv[i].y);
                acc2[i][0] = f2fma(pp, vv[1].x, acc2[i][0]);
                acc2[i][1] = f2fma(pp, vv[1].y, acc2[i][1]);
                pp = f2pack(pv[i].z, pv[i].z);
                acc2[i][0] = f2fma(pp, vv[2].x, acc2[i][0]);
                acc2[i][1] = f2fma(pp, vv[2].y, acc2[i][1]);
                pp = f2pack(pv[i].w, pv[i].w);
                acc2[i][0] = f2fma(pp, vv[3].x, acc2[i][0]);
                acc2[i][1] = f2fma(pp, vv[3].y, acc2[i][1]);
            }
        }
    }

    // ---- write ctx [B,S,E] : O cols = tx*4..+3, float4 stores ----
    #pragma unroll
    for (int i = 0; i < 8; i++) {
        float inv = 1.0f / l_i[i];
        int srow = qt * 128 + ty * 8 + i;
        float o0, o1, o2, o3;
        f2unpack(acc2[i][0], o0, o1);
        f2unpack(acc2[i][1], o2, o3);
        float4 o = make_float4(o0 * inv, o1 * inv, o2 * inv, o3 * inv);
        *(float4*)&g_ctx[((size_t)b * SS + srow) * EE + h * DD + tx * 4] = o;
    }
}

// ---------------------------------------------------------------------------
// launch
// ---------------------------------------------------------------------------
extern "C" void kernel_launch(void* const* d_in, const int* in_sizes, int n_in,
                              void* d_out, int out_size)
{
    const float* x  = (const float*)d_in[0];
    const float* Wq = (const float*)d_in[1];
    const float* bq = (const float*)d_in[2];
    const float* Wk = (const float*)d_in[3];
    const float* bk = (const float*)d_in[4];
    const float* Wv = (const float*)d_in[5];
    const float* bv = (const float*)d_in[6];
    const float* Wo = (const float*)d_in[7];
    const float* bo = (const float*)d_in[8];
    float* out = (float*)d_out;

    float *qp, *kp, *vp, *cp;
    cudaGetSymbolAddress((void**)&qp, g_Q);
    cudaGetSymbolAddress((void**)&kp, g_K);
    cudaGetSymbolAddress((void**)&vp, g_V);
    cudaGetSymbolAddress((void**)&cp, g_ctx);

    dim3 gg(EE / 128, MM / 128);   // (6, 64)
    sgemm_kernel<<<gg, 256>>>(x, Wq, bq, qp, 1);
    sgemm_kernel<<<gg, 256>>>(x, Wk, bk, kp, 1);
    sgemm_kernel<<<gg, 256>>>(x, Wv, bv, vp, 1);

    cudaFuncSetAttribute(flash_kernel, cudaFuncAttributeMaxDynamicSharedMemorySize,
                         FLASH_SMEM_BYTES);
    dim3 fg(SS / 128, HH, BB);     // (32, 12, 2)
    flash_kernel<<<fg, 256, FLASH_SMEM_BYTES>>>();

    sgemm_kernel<<<gg, 256>>>(cp, Wo, bo, out, 0);
}